// round 1
// baseline (speedup 1.0000x reference)
#include <cuda_runtime.h>
#include <cuda_bf16.h>
#include <cstdint>

#define B 4096

// ---------------- scratch (device globals; no allocation allowed) ----------------
__device__ float g_out1[B * 32 * 14 * 14];   // after conv1 block
__device__ float g_out2[B * 32 * 7 * 7];     // after conv2 block
__device__ float g_out3[B * 32 * 3 * 3];     // after conv3 block (pre-BN)
__device__ float g_w2r[32 * 9 * 32];         // cw2 rearranged [ic][k][oc]
__device__ float g_w3r[32 * 9 * 32];         // cw3 rearranged [ic][k][oc]
__device__ float g_stats[64];                // sum[32], sumsq[32]
__device__ float g_scale[32], g_shift[32];   // BN affine
__device__ float g_Wc[3 * 288 * 10];         // composed expert weights
__device__ float g_bc[3 * 10];               // composed expert bias

// ---------------- prep: rearrange conv2/conv3 weights, zero stats ----------------
__global__ void prep_kernel(const float* __restrict__ cw2, const float* __restrict__ cw3) {
    int i = blockIdx.x * blockDim.x + threadIdx.x;
    if (i < 64) g_stats[i] = 0.f;
    if (i < 9216) {
        int oc = i / 288;
        int rem = i - oc * 288;      // ic*9 + k
        g_w2r[rem * 32 + oc] = cw2[i];
        g_w3r[rem * 32 + oc] = cw3[i];
    }
}

// ---------------- conv1 (1->32) + relu + pool : [B,1,28,28] -> [B,32,14,14] ------
__global__ void conv1_kernel(const float* __restrict__ x,
                             const float* __restrict__ cw1,
                             const float* __restrict__ cb1) {
    __shared__ float w1s[288];
    __shared__ float b1s[32];
    int tid = threadIdx.x;
    for (int i = tid; i < 288; i += 256) w1s[i] = cw1[i];
    if (tid < 32) b1s[tid] = cb1[tid];
    __syncthreads();

    int idx = blockIdx.x * 256 + tid;          // 0 .. B*196-1 (exact)
    int b = idx / 196;
    int pos = idx - b * 196;
    int ph = pos / 14, pw = pos - ph * 14;

    // 4x4 input patch, rows 2ph-1..2ph+2, cols 2pw-1..2pw+2, zero padded
    float p[4][4];
    const float* xb = x + b * 784;
#pragma unroll
    for (int r = 0; r < 4; r++) {
        int ir = 2 * ph - 1 + r;
#pragma unroll
        for (int c = 0; c < 4; c++) {
            int ic = 2 * pw - 1 + c;
            p[r][c] = (ir >= 0 && ir < 28 && ic >= 0 && ic < 28) ? xb[ir * 28 + ic] : 0.f;
        }
    }

    float* dst = g_out1 + b * 6272 + pos;      // [b][oc][196]
#pragma unroll 4
    for (int oc = 0; oc < 32; oc++) {
        float a0 = 0.f, a1 = 0.f, a2 = 0.f, a3 = 0.f;
#pragma unroll
        for (int kh = 0; kh < 3; kh++)
#pragma unroll
            for (int kw = 0; kw < 3; kw++) {
                float w = w1s[oc * 9 + kh * 3 + kw];
                a0 += p[kh][kw] * w;
                a1 += p[kh][kw + 1] * w;
                a2 += p[kh + 1][kw] * w;
                a3 += p[kh + 1][kw + 1] * w;
            }
        float v = fmaxf(fmaxf(a0, a1), fmaxf(a2, a3)) + b1s[oc];
        dst[oc * 196] = fmaxf(v, 0.f);
    }
}

// ---------------- conv2 (32->32) + relu + pool : [B,32,14,14] -> [B,32,7,7] ------
__global__ void __launch_bounds__(224) conv2_kernel(const float* __restrict__ cb2) {
    __shared__ float sIn[32 * 16 * 16];        // padded [ic][16][16]
    int b = blockIdx.x;
    int tid = threadIdx.x;
    for (int i = tid; i < 8192; i += 224) sIn[i] = 0.f;
    __syncthreads();
    const float* src = g_out1 + b * 6272;
    for (int i = tid; i < 6272; i += 224) {
        int ic = i / 196;
        int rem = i - ic * 196;
        int r = rem / 14, c = rem - r * 14;
        sIn[ic * 256 + (r + 1) * 16 + (c + 1)] = src[i];
    }
    __syncthreads();

    if (tid < 196) {
        int ocg = tid / 49;
        int pos = tid - ocg * 49;
        int ph = pos / 7, pw = pos - ph * 7;

        float acc[8][4];
#pragma unroll
        for (int o = 0; o < 8; o++)
#pragma unroll
            for (int q = 0; q < 4; q++) acc[o][q] = 0.f;

        const float* sbase = sIn + (2 * ph) * 16 + 2 * pw;  // halo already +1 offset
        for (int ic = 0; ic < 32; ic++) {
            const float* sp = sbase + ic * 256;
            float p[4][4];
#pragma unroll
            for (int r = 0; r < 4; r++) {
                float2 u = *(const float2*)(sp + r * 16);
                float2 v = *(const float2*)(sp + r * 16 + 2);
                p[r][0] = u.x; p[r][1] = u.y; p[r][2] = v.x; p[r][3] = v.y;
            }
            const float4* wp = (const float4*)(g_w2r + ic * 288 + ocg * 8);
#pragma unroll
            for (int kh = 0; kh < 3; kh++)
#pragma unroll
                for (int kw = 0; kw < 3; kw++) {
                    int kidx = kh * 3 + kw;
                    float4 wa = __ldg(&wp[kidx * 8]);
                    float4 wb = __ldg(&wp[kidx * 8 + 1]);
#pragma unroll
                    for (int dh = 0; dh < 2; dh++)
#pragma unroll
                        for (int dw = 0; dw < 2; dw++) {
                            float iv = p[kh + dh][kw + dw];
                            int q = dh * 2 + dw;
                            acc[0][q] += iv * wa.x; acc[1][q] += iv * wa.y;
                            acc[2][q] += iv * wa.z; acc[3][q] += iv * wa.w;
                            acc[4][q] += iv * wb.x; acc[5][q] += iv * wb.y;
                            acc[6][q] += iv * wb.z; acc[7][q] += iv * wb.w;
                        }
                }
        }
        float* dst = g_out2 + (b * 32 + ocg * 8) * 49 + pos;
#pragma unroll
        for (int o = 0; o < 8; o++) {
            float v = fmaxf(fmaxf(acc[o][0], acc[o][1]), fmaxf(acc[o][2], acc[o][3]))
                      + __ldg(&cb2[ocg * 8 + o]);
            dst[o * 49] = fmaxf(v, 0.f);
        }
    }
}

// ---------------- conv3 (32->32) + relu + pool(floor) + BN-stat atomics ----------
// [B,32,7,7] -> [B,32,3,3]; only 6x6 conv positions needed (row/col 6 dropped).
#define C3_NB 3
__global__ void __launch_bounds__(128) conv3_kernel(const float* __restrict__ cb3) {
    __shared__ float sm[C3_NB * 32 * 9 * 12];  // padded [im][ic][9][12], 41472 B
    __shared__ float ssum[32], ssq[32];
    int tid = threadIdx.x;
    int b0 = blockIdx.x * C3_NB;

    for (int i = tid; i < C3_NB * 3456; i += 128) sm[i] = 0.f;
    if (tid < 32) { ssum[tid] = 0.f; ssq[tid] = 0.f; }
    __syncthreads();

    for (int idx = tid; idx < C3_NB * 1568; idx += 128) {
        int im = idx / 1568;
        int j = idx - im * 1568;
        int img = b0 + im;
        if (img < B) {
            int ic = j / 49;
            int rem = j - ic * 49;
            int r = rem / 7, c = rem - r * 7;
            sm[im * 3456 + ic * 108 + (r + 1) * 12 + (c + 1)] = g_out2[img * 1568 + j];
        }
    }
    __syncthreads();

    if (tid < C3_NB * 36) {
        int im = tid / 36;
        int img = b0 + im;
        if (img < B) {
            int rem = tid - im * 36;
            int ocg = rem / 9;
            int pos = rem - ocg * 9;
            int ph = pos / 3, pw = pos - ph * 3;

            float acc[8][4];
#pragma unroll
            for (int o = 0; o < 8; o++)
#pragma unroll
                for (int q = 0; q < 4; q++) acc[o][q] = 0.f;

            const float* sbase = sm + im * 3456 + (2 * ph) * 12 + 2 * pw;
            for (int ic = 0; ic < 32; ic++) {
                const float* sp = sbase + ic * 108;
                float p[4][4];
#pragma unroll
                for (int r = 0; r < 4; r++) {
                    float2 u = *(const float2*)(sp + r * 12);
                    float2 v = *(const float2*)(sp + r * 12 + 2);
                    p[r][0] = u.x; p[r][1] = u.y; p[r][2] = v.x; p[r][3] = v.y;
                }
                const float4* wp = (const float4*)(g_w3r + ic * 288 + ocg * 8);
#pragma unroll
                for (int kh = 0; kh < 3; kh++)
#pragma unroll
                    for (int kw = 0; kw < 3; kw++) {
                        int kidx = kh * 3 + kw;
                        float4 wa = __ldg(&wp[kidx * 8]);
                        float4 wb = __ldg(&wp[kidx * 8 + 1]);
#pragma unroll
                        for (int dh = 0; dh < 2; dh++)
#pragma unroll
                            for (int dw = 0; dw < 2; dw++) {
                                float iv = p[kh + dh][kw + dw];
                                int q = dh * 2 + dw;
                                acc[0][q] += iv * wa.x; acc[1][q] += iv * wa.y;
                                acc[2][q] += iv * wa.z; acc[3][q] += iv * wa.w;
                                acc[4][q] += iv * wb.x; acc[5][q] += iv * wb.y;
                                acc[6][q] += iv * wb.z; acc[7][q] += iv * wb.w;
                            }
                    }
            }
#pragma unroll
            for (int o = 0; o < 8; o++) {
                int oc = ocg * 8 + o;
                float v = fmaxf(fmaxf(acc[o][0], acc[o][1]), fmaxf(acc[o][2], acc[o][3]))
                          + __ldg(&cb3[oc]);
                v = fmaxf(v, 0.f);
                g_out3[img * 288 + oc * 9 + pos] = v;
                atomicAdd(&ssum[oc], v);
                atomicAdd(&ssq[oc], v * v);
            }
        }
    }
    __syncthreads();
    if (tid < 32) {
        atomicAdd(&g_stats[tid], ssum[tid]);
        atomicAdd(&g_stats[32 + tid], ssq[tid]);
    }
}

// ---------------- BN finalize -> scale/shift per channel ------------------------
__global__ void bn_finalize_kernel(const float* __restrict__ bn_g,
                                   const float* __restrict__ bn_b) {
    int c = threadIdx.x;
    if (c < 32) {
        const float inv_n = 1.0f / (float)(B * 9);
        float m = g_stats[c] * inv_n;
        float var = g_stats[32 + c] * inv_n - m * m;
        float sc = bn_g[c] * rsqrtf(var + 1e-5f);
        g_scale[c] = sc;
        g_shift[c] = bn_b[c] - m * sc;
    }
}

// ---------------- compose the 3 chained expert linears per action ---------------
__global__ void compose_kernel(const float* __restrict__ ew1, const float* __restrict__ eb1,
                               const float* __restrict__ ew2, const float* __restrict__ eb2,
                               const float* __restrict__ ew3, const float* __restrict__ eb3) {
    __shared__ float E3s[1280];   // [128][10]
    __shared__ float C1s[1280];   // E2@E3  [128][10]
    int a = blockIdx.x;
    int tid = threadIdx.x;
    for (int i = tid; i < 1280; i += 128) E3s[i] = ew3[a * 1280 + i];
    __syncthreads();
    {
        float s[10];
#pragma unroll
        for (int o = 0; o < 10; o++) s[o] = 0.f;
        const float* e2r = ew2 + a * 16384 + tid * 128;
        for (int j = 0; j < 128; j++) {
            float e = e2r[j];
#pragma unroll
            for (int o = 0; o < 10; o++) s[o] += e * E3s[j * 10 + o];
        }
#pragma unroll
        for (int o = 0; o < 10; o++) C1s[tid * 10 + o] = s[o];
    }
    __syncthreads();
    if (tid < 10) {
        float bb = eb3[a * 10 + tid];
        for (int i = 0; i < 128; i++) {
            bb += eb2[a * 128 + i] * E3s[i * 10 + tid];
            bb += eb1[a * 128 + i] * C1s[i * 10 + tid];
        }
        g_bc[a * 10 + tid] = bb;
    }
    for (int k = tid; k < 288; k += 128) {
        float s[10];
#pragma unroll
        for (int o = 0; o < 10; o++) s[o] = 0.f;
        const float* e1r = ew1 + a * 36864 + k * 128;
        for (int i = 0; i < 128; i++) {
            float e = e1r[i];
#pragma unroll
            for (int o = 0; o < 10; o++) s[o] += e * C1s[i * 10 + o];
        }
#pragma unroll
        for (int o = 0; o < 10; o++) g_Wc[(a * 288 + k) * 10 + o] = s[o];
    }
}

// ---------------- MLP + argmax routing + composed selection ---------------------
// 8 warps/block, 2 examples per warp => 16 examples/block, grid 256.
__global__ void __launch_bounds__(256) mlp_kernel(
    const float* __restrict__ pw1, const float* __restrict__ pb1,
    const float* __restrict__ pw2, const float* __restrict__ pb2,
    const float* __restrict__ pw3, const float* __restrict__ pb3,
    float* __restrict__ out, int write_actions) {
    __shared__ float ys[8 * 2 * 288];
    __shared__ float hA[8 * 2 * 128];
    __shared__ float hB[8 * 2 * 128];
    int w = threadIdx.x >> 5;
    int lane = threadIdx.x & 31;
    float* yw = ys + w * 576;
    float* ha = hA + w * 256;
    float* hb = hB + w * 256;
    int e0 = blockIdx.x * 16 + w * 2;

    // load + BN
    for (int idx = lane; idx < 576; idx += 32) {
        int e = idx / 288;
        int k = idx - e * 288;
        int c = k / 9;
        yw[idx] = g_out3[(e0 + e) * 288 + k] * g_scale[c] + g_shift[c];
    }
    __syncwarp();

    // layer1: 288 -> 128, relu
    {
        float acc[2][4];
#pragma unroll
        for (int m = 0; m < 4; m++) {
            float bv = __ldg(&pb1[lane + 32 * m]);
            acc[0][m] = bv; acc[1][m] = bv;
        }
        for (int k = 0; k < 288; k++) {
            const float* wr = pw1 + k * 128 + lane;
            float w0 = wr[0], w1 = wr[32], w2 = wr[64], w3 = wr[96];
            float y0 = yw[k], y1 = yw[288 + k];
            acc[0][0] += y0 * w0; acc[0][1] += y0 * w1; acc[0][2] += y0 * w2; acc[0][3] += y0 * w3;
            acc[1][0] += y1 * w0; acc[1][1] += y1 * w1; acc[1][2] += y1 * w2; acc[1][3] += y1 * w3;
        }
#pragma unroll
        for (int e = 0; e < 2; e++)
#pragma unroll
            for (int m = 0; m < 4; m++)
                ha[e * 128 + lane + 32 * m] = fmaxf(acc[e][m], 0.f);
    }
    __syncwarp();

    // layer2: 128 -> 128, relu
    {
        float acc[2][4];
#pragma unroll
        for (int m = 0; m < 4; m++) {
            float bv = __ldg(&pb2[lane + 32 * m]);
            acc[0][m] = bv; acc[1][m] = bv;
        }
        for (int k = 0; k < 128; k++) {
            const float* wr = pw2 + k * 128 + lane;
            float w0 = wr[0], w1 = wr[32], w2 = wr[64], w3 = wr[96];
            float y0 = ha[k], y1 = ha[128 + k];
            acc[0][0] += y0 * w0; acc[0][1] += y0 * w1; acc[0][2] += y0 * w2; acc[0][3] += y0 * w3;
            acc[1][0] += y1 * w0; acc[1][1] += y1 * w1; acc[1][2] += y1 * w2; acc[1][3] += y1 * w3;
        }
#pragma unroll
        for (int e = 0; e < 2; e++)
#pragma unroll
            for (int m = 0; m < 4; m++)
                hb[e * 128 + lane + 32 * m] = fmaxf(acc[e][m], 0.f);
    }
    __syncwarp();

    // layer3 logits + argmax + composed selection, per example
    for (int e = 0; e < 2; e++) {
        float p0 = 0.f, p1 = 0.f, p2 = 0.f;
#pragma unroll
        for (int kk = 0; kk < 4; kk++) {
            int k = lane + 32 * kk;
            float hv = hb[e * 128 + k];
            const float* wr = pw3 + k * 3;
            p0 += hv * wr[0]; p1 += hv * wr[1]; p2 += hv * wr[2];
        }
#pragma unroll
        for (int off = 16; off > 0; off >>= 1) {
            p0 += __shfl_down_sync(0xffffffffu, p0, off);
            p1 += __shfl_down_sync(0xffffffffu, p1, off);
            p2 += __shfl_down_sync(0xffffffffu, p2, off);
        }
        int a = 0;
        if (lane == 0) {
            p0 += __ldg(&pb3[0]); p1 += __ldg(&pb3[1]); p2 += __ldg(&pb3[2]);
            float best = p0;
            if (p1 > best) { best = p1; a = 1; }
            if (p2 > best) { a = 2; }
        }
        a = __shfl_sync(0xffffffffu, a, 0);

        float po[10];
#pragma unroll
        for (int o = 0; o < 10; o++) po[o] = 0.f;
        const float* Wb = g_Wc + a * 2880;
        const float* ye = yw + e * 288;
#pragma unroll
        for (int kk = 0; kk < 9; kk++) {
            int k = lane + 32 * kk;
            float yv = ye[k];
            const float* wr = Wb + k * 10;
#pragma unroll
            for (int o = 0; o < 10; o++) po[o] += yv * wr[o];
        }
#pragma unroll
        for (int off = 16; off > 0; off >>= 1) {
#pragma unroll
            for (int o = 0; o < 10; o++) po[o] += __shfl_down_sync(0xffffffffu, po[o], off);
        }
        if (lane == 0) {
            int g = e0 + e;
#pragma unroll
            for (int o = 0; o < 10; o++) out[g * 10 + o] = po[o] + g_bc[a * 10 + o];
            if (write_actions) out[B * 10 + g] = (float)a;
        }
    }
}

// ---------------- launch ---------------------------------------------------------
extern "C" void kernel_launch(void* const* d_in, const int* in_sizes, int n_in,
                              void* d_out, int out_size) {
    const float* x    = (const float*)d_in[0];
    const float* cw1  = (const float*)d_in[1];
    const float* cb1  = (const float*)d_in[2];
    const float* cw2  = (const float*)d_in[3];
    const float* cb2  = (const float*)d_in[4];
    const float* cw3  = (const float*)d_in[5];
    const float* cb3  = (const float*)d_in[6];
    const float* bn_g = (const float*)d_in[7];
    const float* bn_b = (const float*)d_in[8];
    const float* pw1  = (const float*)d_in[9];
    const float* pb1  = (const float*)d_in[10];
    const float* pw2  = (const float*)d_in[11];
    const float* pb2  = (const float*)d_in[12];
    const float* pw3  = (const float*)d_in[13];
    const float* pb3  = (const float*)d_in[14];
    const float* ew1  = (const float*)d_in[15];
    const float* eb1  = (const float*)d_in[16];
    const float* ew2  = (const float*)d_in[17];
    const float* eb2  = (const float*)d_in[18];
    const float* ew3  = (const float*)d_in[19];
    const float* eb3  = (const float*)d_in[20];
    float* out = (float*)d_out;
    int write_actions = (out_size >= B * 10 + B) ? 1 : 0;

    prep_kernel<<<36, 256>>>(cw2, cw3);
    conv1_kernel<<<(B * 196) / 256, 256>>>(x, cw1, cb1);
    conv2_kernel<<<B, 224>>>(cb2);
    conv3_kernel<<<(B + C3_NB - 1) / C3_NB, 128>>>(cb3);
    bn_finalize_kernel<<<1, 32>>>(bn_g, bn_b);
    compose_kernel<<<3, 128>>>(ew1, eb1, ew2, eb2, ew3, eb3);
    mlp_kernel<<<B / 16, 256>>>(pw1, pb1, pw2, pb2, pw3, pb3, out, write_actions);
}